// round 6
// baseline (speedup 1.0000x reference)
#include <cuda_runtime.h>
#include <cuda_bf16.h>

#define NB 4
#define NC 128
#define HWP (512*512)
#define NL 512
#define TILE 4096
#define THREADS 512
#define KCAP 16

// dynamic smem layout (bytes)
#define OFF_SX     0        // float4 sx[TILE]      = 65536 (swizzled, channel-interleaved)
#define OFF_SLAB   65536    // ushort slab[TILE]    = 8192
#define OFF_SOFF   73728    // ushort soffs[TILE]   = 8192 (swizzled byte offsets, sorted by label)
#define OFF_CNT    81920    // int cnt[NL]          = 2048
#define OFF_START  83968    // int start[NL]        = 2048
#define OFF_CURSOR 86016    // int cursor[NL]       = 2048
#define OFF_WSUM   88064    // int wsum[16]         = 64
#define SMEM_BYTES 88128

__device__ int g_counts[NB * NL];
__device__ int g_lab64;   // 1 if labels are int64, 0 if int32

__device__ __forceinline__ void red4(float* p, float a, float b, float c, float d) {
    asm volatile("red.global.add.v4.f32 [%0], {%1,%2,%3,%4};"
                 :: "l"(p), "f"(a), "f"(b), "f"(c), "f"(d) : "memory");
}

__device__ __forceinline__ float4 lds128(unsigned int addr) {
    float4 v;
    asm volatile("ld.shared.v4.f32 {%0,%1,%2,%3}, [%4];"
                 : "=f"(v.x), "=f"(v.y), "=f"(v.z), "=f"(v.w) : "r"(addr));
    return v;
}
__device__ __forceinline__ void sts128(unsigned int addr, float a, float b, float c, float d) {
    asm volatile("st.shared.v4.f32 [%0], {%1,%2,%3,%4};"
                 :: "r"(addr), "f"(a), "f"(b), "f"(c), "f"(d));
}

__device__ __forceinline__ unsigned int swz(int pix) {   // 16B-aligned conflict-free swizzle
    return (unsigned int)((pix ^ ((pix >> 3) & 7)) * 16);
}

// Probe label dtype: int64-LE labels in [0,512) have all odd 32-bit words == 0.
__global__ void detect_kernel(const unsigned int* __restrict__ lab32) {
    int is64 = 1;
    for (int i = 0; i < 128; i++) {
        if (lab32[2 * i + 1] != 0u || lab32[2 * i] >= 512u) { is64 = 0; break; }
    }
    g_lab64 = is64;
}

__global__ void zero_kernel(float* __restrict__ out) {
    int i = blockIdx.x * 256 + threadIdx.x;
    if (i < NB * NL * NC) out[i] = 0.0f;
    if (i < NB * NL) g_counts[i] = 0;
}

__global__ __launch_bounds__(THREADS, 2) void accum_kernel(
    const float* __restrict__ x,
    const void* __restrict__ lab_raw,
    float* __restrict__ out)
{
    extern __shared__ char smem[];
    unsigned short* slab   = (unsigned short*)(smem + OFF_SLAB);
    unsigned short* soffs  = (unsigned short*)(smem + OFF_SOFF);
    int*            cnt    = (int*)(smem + OFF_CNT);
    int*            start  = (int*)(smem + OFF_START);
    int*            cursor = (int*)(smem + OFF_CURSOR);
    int*            wsum   = (int*)(smem + OFF_WSUM);

    const int b    = blockIdx.y;
    const int p0   = blockIdx.x * TILE;
    const int tid  = threadIdx.x;
    const int lane = tid & 31;
    const int wid  = tid >> 5;

    const unsigned int sx_base =
        (unsigned int)__cvta_generic_to_shared(smem) + OFF_SX;

    cnt[tid] = 0;   // THREADS == NL
    __syncthreads();

    // ---- load labels, build histogram ----
    if (g_lab64) {
        const long long* lb = (const long long*)lab_raw + (size_t)b * HWP + p0;
        for (int i = tid; i < TILE; i += THREADS) {
            int l = ((int)lb[i]) & (NL - 1);
            slab[i] = (unsigned short)l;
            atomicAdd(&cnt[l], 1);
        }
    } else {
        const int* lb = (const int*)lab_raw + (size_t)b * HWP + p0;
        for (int i = tid; i < TILE; i += THREADS) {
            int l = lb[i] & (NL - 1);
            slab[i] = (unsigned short)l;
            atomicAdd(&cnt[l], 1);
        }
    }
    __syncthreads();

    // ---- exclusive prefix sum over cnt[512] ----
    int v = cnt[tid];
    int s = v;
    #pragma unroll
    for (int d = 1; d < 32; d <<= 1) {
        int n2 = __shfl_up_sync(0xffffffffu, s, d);
        if (lane >= d) s += n2;
    }
    if (lane == 31) wsum[wid] = s;
    __syncthreads();
    if (tid < 16) {
        int t = wsum[tid];
        #pragma unroll
        for (int d = 1; d < 16; d <<= 1) {
            int n2 = __shfl_up_sync(0x0000ffffu, t, d);
            if ((int)tid >= d) t += n2;
        }
        wsum[tid] = t;
    }
    __syncthreads();
    int excl = s - v + (wid ? wsum[wid - 1] : 0);
    start[tid]  = excl;
    cursor[tid] = excl;
    if (v) atomicAdd(&g_counts[b * NL + tid], v);
    __syncthreads();

    // ---- scatter: swizzled byte-offsets sorted by label ----
    for (int i = tid; i < TILE; i += THREADS) {
        int l = slab[i];
        int pos = atomicAdd(&cursor[l], 1);
        soffs[pos] = (unsigned short)swz(i);
    }
    __syncthreads();

    // ---- cache this thread's label-run offsets in registers (packed 2/reg) ----
    const int n    = cnt[tid];
    const int base = start[tid];
    unsigned int offr[KCAP / 2];
    #pragma unroll
    for (int jj = 0; jj < KCAP / 2; jj++) {
        unsigned int lo = (2 * jj     < n) ? soffs[base + 2 * jj]     : 0u;
        unsigned int hi = (2 * jj + 1 < n) ? soffs[base + 2 * jj + 1] : 0u;
        offr[jj] = lo | (hi << 16);
    }

    // ---- per 4-channel group: stage transposed+swizzled, vector gather, one red4 ----
    const float* xb = x + (size_t)b * NC * HWP + p0;
    float*       ob = out + (size_t)b * NL * NC;

    #pragma unroll 1
    for (int cg = 0; cg < NC / 4; cg++) {
        const float* xp = xb + (size_t)(4 * cg) * HWP;

        // stage: 2 pixel-quads per thread, 4 channels -> float4-per-pixel, swizzled
        #pragma unroll
        for (int h = 0; h < 2; h++) {
            int q = tid + h * THREADS;           // pixel-quad index [0,1024)
            const float4 a0 = *(const float4*)(xp + 4 * q);
            const float4 a1 = *(const float4*)(xp + (size_t)HWP     + 4 * q);
            const float4 a2 = *(const float4*)(xp + (size_t)2 * HWP + 4 * q);
            const float4 a3 = *(const float4*)(xp + (size_t)3 * HWP + 4 * q);
            sts128(sx_base + swz(4 * q    ), a0.x, a1.x, a2.x, a3.x);
            sts128(sx_base + swz(4 * q + 1), a0.y, a1.y, a2.y, a3.y);
            sts128(sx_base + swz(4 * q + 2), a0.z, a1.z, a2.z, a3.z);
            sts128(sx_base + swz(4 * q + 3), a0.w, a1.w, a2.w, a3.w);
        }
        __syncthreads();

        float c0 = 0.f, c1 = 0.f, c2 = 0.f, c3 = 0.f;
        #pragma unroll
        for (int jj = 0; jj < KCAP; jj++) {
            if (jj < n) {
                unsigned int off = (jj & 1) ? (offr[jj >> 1] >> 16)
                                            : (offr[jj >> 1] & 0xFFFFu);
                float4 vv = lds128(sx_base + off);
                c0 += vv.x; c1 += vv.y; c2 += vv.z; c3 += vv.w;
            }
        }
        #pragma unroll 1
        for (int j = KCAP; j < n; j++) {          // rare Poisson tail
            float4 vv = lds128(sx_base + soffs[base + j]);
            c0 += vv.x; c1 += vv.y; c2 += vv.z; c3 += vv.w;
        }

        if (n) red4(ob + tid * NC + 4 * cg, c0, c1, c2, c3);
        __syncthreads();
    }
}

__global__ void finalize_kernel(float* __restrict__ out) {
    int i = blockIdx.x * 256 + threadIdx.x;
    if (i >= NB * NL * NC) return;
    int bl = i / NC;
    int c = g_counts[bl];
    float cnt = (float)(c > 1 ? c : 1);
    out[i] = out[i] / cnt;
}

extern "C" void kernel_launch(void* const* d_in, const int* in_sizes, int n_in,
                              void* d_out, int out_size) {
    // Resolve input binding by element count — x has 134217728 elements,
    // label_maps has 1048576. Do not trust ordering.
    const float* x;
    const void*  lab;
    if (in_sizes[0] > in_sizes[1]) {
        x   = (const float*)d_in[0];
        lab = d_in[1];
    } else {
        x   = (const float*)d_in[1];
        lab = d_in[0];
    }
    float* out = (float*)d_out;

    cudaFuncSetAttribute(accum_kernel,
                         cudaFuncAttributeMaxDynamicSharedMemorySize, SMEM_BYTES);

    detect_kernel<<<1, 1>>>((const unsigned int*)lab);

    int ztot = NB * NL * NC;  // 262144
    zero_kernel<<<(ztot + 255) / 256, 256>>>(out);

    dim3 grid(HWP / TILE, NB);  // 64 x 4 = 256 CTAs, one wave at 2 CTA/SM
    accum_kernel<<<grid, THREADS, SMEM_BYTES>>>(x, lab, out);

    finalize_kernel<<<(ztot + 255) / 256, 256>>>(out);
}